// round 6
// baseline (speedup 1.0000x reference)
#include <cuda_runtime.h>
#include <cuda_fp16.h>
#include <cstdint>

// Problem dims
#define NBATCH 32
#define NT     2048
#define ND     512
#define NU     512

#define LDA 520   // smem row stride in fp16 elems (pad: 260 words -> conflict-free)

// ---------------- device scratch (no allocs allowed) ----------------
__device__ float   g_u[NBATCH * NT];        // raw scores u[b,t] (pre-mask)
__device__ __half  g_w1t[NU * ND];          // W1 transposed [n][k] fp16
__device__ float   g_w2q[NBATCH * NU];      // query @ W2

// ==================== kernel 1: W1 transpose + fp16 convert (tiled) ====================
__global__ void prep_w1t(const float* __restrict__ W1) {
    __shared__ float t[32][33];
    int n0 = blockIdx.x * 32, k0 = blockIdx.y * 32;
    for (int i = threadIdx.y; i < 32; i += 8)
        t[i][threadIdx.x] = W1[(size_t)(k0 + i) * NU + n0 + threadIdx.x];
    __syncthreads();
    for (int i = threadIdx.y; i < 32; i += 8)
        g_w1t[(size_t)(n0 + i) * ND + k0 + threadIdx.x] = __float2half_rn(t[threadIdx.x][i]);
}

// ==================== kernel 2: w2q = query @ W2 (fp32 exact) ====================
__global__ void prep_w2q(const float* __restrict__ query, const float* __restrict__ W2) {
    int b = blockIdx.x, tid = threadIdx.x;           // 512 threads
    __shared__ float q[ND];
    q[tid] = query[b * ND + tid];
    __syncthreads();
    float s = 0.f;
#pragma unroll 8
    for (int d = 0; d < ND; d++) s += q[d] * W2[(size_t)d * NU + tid];
    g_w2q[b * NU + tid] = s;
}

// ---------------- mma.sync m16n8k16 fp16 in, fp32 accum ----------------
__device__ __forceinline__ void mma16816(float* c, uint32_t a0, uint32_t a1,
                                         uint32_t a2, uint32_t a3,
                                         uint32_t b0, uint32_t b1) {
    asm volatile(
        "mma.sync.aligned.m16n8k16.row.col.f32.f16.f16.f32 "
        "{%0,%1,%2,%3}, {%4,%5,%6,%7}, {%8,%9}, {%0,%1,%2,%3};\n"
        : "+f"(c[0]), "+f"(c[1]), "+f"(c[2]), "+f"(c[3])
        : "r"(a0), "r"(a1), "r"(a2), "r"(a3), "r"(b0), "r"(b1));
}

__device__ __forceinline__ float fast_tanh(float x) {
    float e = __expf(2.0f * x);
    return 1.0f - 2.0f / (e + 1.0f);                 // inf-safe
}

// ---------------- smem layout for attn_main ----------------
// sA: 128 x LDA fp16 = 133120 B
// sB:  64 x LDA fp16 =  66560 B
// s_w2q: 512 f32, s_V: 512 f32, s_red: 256 f32
#define SM_A     0
#define SM_B     (128 * LDA * 2)
#define SM_W2Q   (SM_B + 64 * LDA * 2)
#define SM_V     (SM_W2Q + 512 * 4)
#define SM_RED   (SM_V + 512 * 4)
#define SMEM_BYTES (SM_RED + 256 * 4)

// ==================== kernel 3: fused GEMM + tanh + V-dot ====================
__global__ void __launch_bounds__(256, 1)
attn_main(const float* __restrict__ value, const float* __restrict__ Vvec) {
    extern __shared__ char smem[];
    __half* sA    = reinterpret_cast<__half*>(smem + SM_A);
    __half* sB    = reinterpret_cast<__half*>(smem + SM_B);
    float*  s_w2q = reinterpret_cast<float*>(smem + SM_W2Q);
    float*  s_V   = reinterpret_cast<float*>(smem + SM_V);
    float*  s_red = reinterpret_cast<float*>(smem + SM_RED);

    const int tid  = threadIdx.x;
    const int wid  = tid >> 5;
    const int lane = tid & 31;
    const int row0 = blockIdx.x * 128;               // global (b*T + t) row
    const int b    = row0 >> 11;                     // row0 / 2048

    // ---- stage A: value[row0:row0+128, :] fp32 -> fp16 smem (padded rows) ----
    const float4* vsrc = reinterpret_cast<const float4*>(value + (size_t)row0 * ND);
    for (int i = tid; i < 128 * 128; i += 256) {     // 16384 float4s
        int r = i >> 7, c4 = i & 127;
        float4 v = vsrc[r * 128 + c4];
        __half2 lo = __floats2half2_rn(v.x, v.y);
        __half2 hi = __floats2half2_rn(v.z, v.w);
        uint2 pk;
        pk.x = *reinterpret_cast<uint32_t*>(&lo);
        pk.y = *reinterpret_cast<uint32_t*>(&hi);
        *reinterpret_cast<uint2*>(sA + (size_t)r * LDA + c4 * 4) = pk;
    }
    for (int i = tid; i < NU; i += 256) {
        s_w2q[i] = g_w2q[b * NU + i];
        s_V[i]   = Vvec[i];
    }

    // warp tiling: 8 warps -> (rg 0..3) x (cg 0..1): 32 rows x 32 cols each
    const int rg = wid & 3, cg = wid >> 2;
    const int gq = lane >> 2, tq = lane & 3;         // groupid / tid-in-group

    float rsum[4] = {0.f, 0.f, 0.f, 0.f};            // [mr][half]

    for (int nb = 0; nb < 8; nb++) {
        if (nb) __syncthreads();                     // prev sB fully consumed
        // ---- stage B chunk: g_w1t rows [nb*64, nb*64+64) ----
        const uint4* bsrc = reinterpret_cast<const uint4*>(g_w1t + (size_t)(nb * 64) * ND);
        for (int i = tid; i < 64 * 64; i += 256) {   // 4096 uint4 (8 fp16 each)
            int n = i >> 6, c8 = i & 63;
            uint4 w = bsrc[n * 64 + c8];
            *reinterpret_cast<uint4*>(sB + (size_t)n * LDA + c8 * 8) = w;
        }
        __syncthreads();

        float acc[8][4];                             // [mr*4+nf][4]
#pragma unroll
        for (int f = 0; f < 8; f++)
#pragma unroll
            for (int j = 0; j < 4; j++) acc[f][j] = 0.f;

#pragma unroll 4
        for (int ks = 0; ks < 32; ks++) {
            const int k0 = ks * 16;
            uint32_t a[2][4];
#pragma unroll
            for (int mr = 0; mr < 2; mr++) {
                const __half* ap = sA + (size_t)(rg * 32 + mr * 16 + gq) * LDA + k0 + tq * 2;
                a[mr][0] = *reinterpret_cast<const uint32_t*>(ap);
                a[mr][1] = *reinterpret_cast<const uint32_t*>(ap + 8 * LDA);
                a[mr][2] = *reinterpret_cast<const uint32_t*>(ap + 8);
                a[mr][3] = *reinterpret_cast<const uint32_t*>(ap + 8 * LDA + 8);
            }
#pragma unroll
            for (int nf = 0; nf < 4; nf++) {
                const __half* bp = sB + (size_t)(cg * 32 + nf * 8 + gq) * LDA + k0 + tq * 2;
                uint32_t b0 = *reinterpret_cast<const uint32_t*>(bp);
                uint32_t b1 = *reinterpret_cast<const uint32_t*>(bp + 8);
                mma16816(acc[0 * 4 + nf], a[0][0], a[0][1], a[0][2], a[0][3], b0, b1);
                mma16816(acc[1 * 4 + nf], a[1][0], a[1][1], a[1][2], a[1][3], b0, b1);
            }
        }

        // ---- epilogue for this 64-col chunk: tanh + V-dot, accumulate per-row ----
#pragma unroll
        for (int mr = 0; mr < 2; mr++)
#pragma unroll
            for (int nf = 0; nf < 4; nf++) {
                const int col = nb * 64 + cg * 32 + nf * 8 + tq * 2;
                const float w0 = s_w2q[col], w1 = s_w2q[col + 1];
                const float v0 = s_V[col],   v1 = s_V[col + 1];
                const float* c = acc[mr * 4 + nf];
                rsum[mr * 2 + 0] += v0 * fast_tanh(c[0] + w0) + v1 * fast_tanh(c[1] + w1);
                rsum[mr * 2 + 1] += v0 * fast_tanh(c[2] + w0) + v1 * fast_tanh(c[3] + w1);
            }
    }

    // reduce across the 4 threads of each quad (tq dimension)
#pragma unroll
    for (int j = 0; j < 4; j++) {
        rsum[j] += __shfl_xor_sync(0xFFFFFFFF, rsum[j], 1);
        rsum[j] += __shfl_xor_sync(0xFFFFFFFF, rsum[j], 2);
    }
    __syncthreads();                                 // sB reads done; reuse barrier
    if (tq == 0) {
#pragma unroll
        for (int mr = 0; mr < 2; mr++)
#pragma unroll
            for (int h = 0; h < 2; h++) {
                int r = rg * 32 + mr * 16 + h * 8 + gq;
                s_red[cg * 128 + r] = rsum[mr * 2 + h];
            }
    }
    __syncthreads();
    if (tid < 128) g_u[row0 + tid] = s_red[tid] + s_red[128 + tid];
}

// ==================== kernel 4: masked softmax -> a ====================
__global__ void softmax_kernel(const int* __restrict__ mask, float* __restrict__ out_a) {
    int b = blockIdx.x, tid = threadIdx.x;           // 256 threads
    __shared__ float red[256];
    const float* ub = g_u + b * NT;
    const int* mb = mask + b * NT;
    float* ab = out_a + b * NT;

    float mx = -3.4e38f;
    for (int t = tid; t < NT; t += 256) {
        float um = ub[t] + (mb[t] ? 0.f : -1e20f);
        mx = fmaxf(mx, um);
    }
    red[tid] = mx; __syncthreads();
    for (int s = 128; s > 0; s >>= 1) { if (tid < s) red[tid] = fmaxf(red[tid], red[tid + s]); __syncthreads(); }
    mx = red[0]; __syncthreads();

    float sum = 0.f;
    for (int t = tid; t < NT; t += 256) {
        float um = ub[t] + (mb[t] ? 0.f : -1e20f);
        float e = expf(um - mx);
        ab[t] = e;
        sum += e;
    }
    red[tid] = sum; __syncthreads();
    for (int s = 128; s > 0; s >>= 1) { if (tid < s) red[tid] += red[tid + s]; __syncthreads(); }
    float inv = 1.0f / red[0];
    for (int t = tid; t < NT; t += 256) ab[t] *= inv;
}

// ==================== kernel 5: exact-fp32 argmax refine + gather ====================
__global__ void __launch_bounds__(256)
argmax_kernel(const float* __restrict__ value, const float* __restrict__ W1,
              const int* __restrict__ mask, const float* __restrict__ Vvec,
              float* __restrict__ out_ctx) {
    int b = blockIdx.x, tid = threadIdx.x;           // 256 threads
    __shared__ float red[256];
    __shared__ float sval[ND];
    __shared__ int   cand[64];
    __shared__ int   ncand;
    __shared__ float best_u;
    __shared__ int   best_t;

    const float* ub = g_u + b * NT;
    const int* mb = mask + b * NT;

    float mx = -3.4e38f;
    for (int t = tid; t < NT; t += 256) {
        float um = ub[t] + (mb[t] ? 0.f : -1e20f);
        mx = fmaxf(mx, um);
    }
    red[tid] = mx; __syncthreads();
    for (int s = 128; s > 0; s >>= 1) { if (tid < s) red[tid] = fmaxf(red[tid], red[tid + s]); __syncthreads(); }
    mx = red[0];
    if (tid == 0) { ncand = 0; best_u = -3.4e38f; best_t = 0; }
    __syncthreads();

    // candidates: within 0.05 of observed max (fp16 GEMM abs error << 0.05)
    for (int t = tid; t < NT; t += 256) {
        float um = ub[t] + (mb[t] ? 0.f : -1e20f);
        if (um > mx - 0.05f) {
            int p = atomicAdd(&ncand, 1);
            if (p < 64) cand[p] = t;
        }
    }
    __syncthreads();
    int nc = min(ncand, 64);

    for (int ci = 0; ci < nc; ci++) {
        int t = cand[ci];
        for (int d = tid; d < ND; d += 256)
            sval[d] = value[((size_t)b * NT + t) * ND + d];
        __syncthreads();
        float p = 0.f;
        for (int n = tid; n < NU; n += 256) {
            float s1 = 0.f;
#pragma unroll 8
            for (int d = 0; d < ND; d++) s1 += sval[d] * W1[(size_t)d * NU + n];
            p += Vvec[n] * tanhf(s1 + g_w2q[b * NU + n]);
        }
        red[tid] = p; __syncthreads();
        for (int s = 128; s > 0; s >>= 1) { if (tid < s) red[tid] += red[tid + s]; __syncthreads(); }
        if (tid == 0) {
            float ue = red[0];
            if (ue > best_u || (ue == best_u && t < best_t)) { best_u = ue; best_t = t; }
        }
        __syncthreads();
    }

    int tb = best_t;
    for (int d = tid; d < ND; d += 256)
        out_ctx[b * ND + d] = value[((size_t)b * NT + tb) * ND + d];
}

// ==================== launch ====================
extern "C" void kernel_launch(void* const* d_in, const int* in_sizes, int n_in,
                              void* d_out, int out_size) {
    const float* value = (const float*)d_in[0];   // [32, 2048, 512]
    const float* query = (const float*)d_in[1];   // [32, 512]
    const int*   mask  = (const int*)d_in[2];     // [32, 2048]
    const float* W1    = (const float*)d_in[3];   // [512, 512]
    const float* W2    = (const float*)d_in[4];   // [512, 512]
    const float* Vv    = (const float*)d_in[5];   // [512]

    float* out     = (float*)d_out;
    float* out_ctx = out;                         // context [32, 512] first
    float* out_a   = out + NBATCH * ND;           // then a [32, 2048]

    cudaFuncSetAttribute(attn_main, cudaFuncAttributeMaxDynamicSharedMemorySize, SMEM_BYTES);

    prep_w1t<<<dim3(NU / 32, ND / 32), dim3(32, 8)>>>(W1);
    prep_w2q<<<NBATCH, 512>>>(query, W2);
    attn_main<<<(NBATCH * NT) / 128, 256, SMEM_BYTES>>>(value, Vv);
    softmax_kernel<<<NBATCH, 256>>>(mask, out_a);
    argmax_kernel<<<NBATCH, 256>>>(value, W1, mask, Vv, out_ctx);
}

// round 7
// speedup vs baseline: 1.0360x; 1.0360x over previous
#include <cuda_runtime.h>
#include <cuda_fp16.h>
#include <cstdint>

// Problem dims
#define NBATCH 32
#define NT     2048
#define ND     512
#define NU     512

#define LDA  520    // smem row stride in fp16 elems (1040B: 16B-aligned, conflict-free)
#define BCH  32     // B n-chunk rows
#define NBCH 16     // number of n-chunks (16*32 = 512)
#define BUFB (BCH * LDA * 2)   // 33280 B per B buffer

// ---------------- device scratch (no allocs allowed) ----------------
__device__ float   g_u[NBATCH * NT];        // raw scores u[b,t] (pre-mask)
__device__ __half  g_w1t[NU * ND];          // W1 transposed [n][k] fp16
__device__ float   g_w2q[NBATCH * NU];      // query @ W2

// ---------------- asm helpers ----------------
__device__ __forceinline__ uint32_t smem_u32(const void* p) {
    uint32_t a;
    asm("{ .reg .u64 t; cvta.to.shared.u64 t, %1; cvt.u32.u64 %0, t; }" : "=r"(a) : "l"(p));
    return a;
}
__device__ __forceinline__ void ldsm4(uint32_t& r0, uint32_t& r1, uint32_t& r2,
                                      uint32_t& r3, uint32_t addr) {
    asm volatile("ldmatrix.sync.aligned.m8n8.x4.shared.b16 {%0,%1,%2,%3}, [%4];"
                 : "=r"(r0), "=r"(r1), "=r"(r2), "=r"(r3) : "r"(addr));
}
__device__ __forceinline__ void cpasync16(uint32_t dst, const void* src) {
    asm volatile("cp.async.cg.shared.global [%0], [%1], 16;" :: "r"(dst), "l"(src));
}
#define CP_COMMIT() asm volatile("cp.async.commit_group;")
#define CP_WAIT0()  asm volatile("cp.async.wait_group 0;")

__device__ __forceinline__ void mma16816(float* c, uint32_t a0, uint32_t a1,
                                         uint32_t a2, uint32_t a3,
                                         uint32_t b0, uint32_t b1) {
    asm volatile(
        "mma.sync.aligned.m16n8k16.row.col.f32.f16.f16.f32 "
        "{%0,%1,%2,%3}, {%4,%5,%6,%7}, {%8,%9}, {%0,%1,%2,%3};\n"
        : "+f"(c[0]), "+f"(c[1]), "+f"(c[2]), "+f"(c[3])
        : "r"(a0), "r"(a1), "r"(a2), "r"(a3), "r"(b0), "r"(b1));
}

__device__ __forceinline__ float fast_tanh(float x) {
    float e = __expf(2.0f * x);
    return 1.0f - __fdividef(2.0f, e + 1.0f);        // inf-safe
}

// ---------------- smem layout for attn_main ----------------
#define SM_A     0                          // 128 x LDA fp16 = 133120
#define SM_B     (128 * LDA * 2)            // 2 x 33280 = 66560
#define SM_W2Q   (SM_B + 2 * BUFB)          // 512 f32
#define SM_V     (SM_W2Q + 512 * 4)         // 512 f32
#define SM_RED   (SM_V + 512 * 4)           // 256 f32
#define SMEM_BYTES (SM_RED + 256 * 4)       // 204800

// ==================== kernel 1: W1 transpose + fp16 convert (tiled) ====================
__global__ void prep_w1t(const float* __restrict__ W1) {
    __shared__ float t[32][33];
    int n0 = blockIdx.x * 32, k0 = blockIdx.y * 32;
    for (int i = threadIdx.y; i < 32; i += 8)
        t[i][threadIdx.x] = W1[(size_t)(k0 + i) * NU + n0 + threadIdx.x];
    __syncthreads();
    for (int i = threadIdx.y; i < 32; i += 8)
        g_w1t[(size_t)(n0 + i) * ND + k0 + threadIdx.x] = __float2half_rn(t[threadIdx.x][i]);
}

// ==================== kernel 2: w2q = query @ W2 (fp32 exact) ====================
__global__ void prep_w2q(const float* __restrict__ query, const float* __restrict__ W2) {
    int b = blockIdx.x, tid = threadIdx.x;           // 512 threads
    __shared__ float q[ND];
    q[tid] = query[b * ND + tid];
    __syncthreads();
    float s = 0.f;
#pragma unroll 8
    for (int d = 0; d < ND; d++) s += q[d] * W2[(size_t)d * NU + tid];
    g_w2q[b * NU + tid] = s;
}

// ==================== kernel 3: fused GEMM + tanh + V-dot ====================
// 512 threads = 16 warps: rg = wid&7 (16-row tile), cg = wid>>3 (16-col tile per chunk)
__global__ void __launch_bounds__(512, 1)
attn_main(const float* __restrict__ value, const float* __restrict__ Vvec) {
    extern __shared__ char smem[];
    __half* sA    = reinterpret_cast<__half*>(smem + SM_A);
    float*  s_w2q = reinterpret_cast<float*>(smem + SM_W2Q);
    float*  s_V   = reinterpret_cast<float*>(smem + SM_V);
    float*  s_red = reinterpret_cast<float*>(smem + SM_RED);

    const uint32_t sA_u = smem_u32(smem) + SM_A;
    const uint32_t sB_u = smem_u32(smem) + SM_B;

    const int tid  = threadIdx.x;
    const int wid  = tid >> 5;
    const int lane = tid & 31;
    const int row0 = blockIdx.x * 128;               // global (b*T + t) row
    const int b    = row0 >> 11;

    // ---- prefetch B chunk 0 into buf 0 (cp.async, overlaps A conversion) ----
    {
        const char* bsrc = reinterpret_cast<const char*>(g_w1t);   // chunk 0
        for (int i = tid; i < 2048; i += 512) {       // 32 rows x 64 x 16B
            int r = i >> 6, c16 = i & 63;
            cpasync16(sB_u + r * (LDA * 2) + c16 * 16, bsrc + r * 1024 + c16 * 16);
        }
        CP_COMMIT();
    }

    // ---- stage A: value[row0:row0+128, :] fp32 -> fp16 smem (padded rows) ----
    const float4* vsrc = reinterpret_cast<const float4*>(value + (size_t)row0 * ND);
    for (int i = tid; i < 128 * 128; i += 512) {     // 16384 float4s
        int r = i >> 7, c4 = i & 127;
        float4 v = vsrc[r * 128 + c4];
        __half2 lo = __floats2half2_rn(v.x, v.y);
        __half2 hi = __floats2half2_rn(v.z, v.w);
        uint2 pk;
        pk.x = *reinterpret_cast<uint32_t*>(&lo);
        pk.y = *reinterpret_cast<uint32_t*>(&hi);
        *reinterpret_cast<uint2*>(sA + (size_t)r * LDA + c4 * 4) = pk;
    }
    if (tid < 512) {
        s_w2q[tid] = g_w2q[b * NU + tid];
        s_V[tid]   = Vvec[tid];
    }

    const int rg = wid & 7, cg = wid >> 3;
    const int gq = lane >> 2, tq = lane & 3;
    const int m0 = rg * 16;

    // per-lane ldmatrix base addresses (k0 = 0)
    const int rowA = m0 + (lane & 7) + ((lane >> 3) & 1) * 8;
    const uint32_t addrA0 = sA_u + (uint32_t)(rowA * LDA + (lane >> 4) * 8) * 2;
    const int rowB = cg * 16 + (lane & 7) + ((lane >> 4) & 1) * 8;
    const uint32_t addrB0_rel = (uint32_t)(rowB * LDA + ((lane >> 3) & 1) * 8) * 2;

    float rsum[2] = {0.f, 0.f};                      // rows m0+gq, m0+8+gq

    for (int nb = 0; nb < NBCH; nb++) {
        CP_WAIT0();
        __syncthreads();                             // buf(nb&1) ready; prev compute done
        if (nb + 1 < NBCH) {                         // prefetch next into other buf
            const char* bsrc = reinterpret_cast<const char*>(g_w1t + (size_t)(nb + 1) * BCH * ND);
            uint32_t bufo = ((nb + 1) & 1) * BUFB;
            for (int i = tid; i < 2048; i += 512) {
                int r = i >> 6, c16 = i & 63;
                cpasync16(sB_u + bufo + r * (LDA * 2) + c16 * 16, bsrc + r * 1024 + c16 * 16);
            }
            CP_COMMIT();
        }

        const uint32_t addrB0 = sB_u + (nb & 1) * BUFB + addrB0_rel;
        float acc[2][4];
#pragma unroll
        for (int f = 0; f < 2; f++)
#pragma unroll
            for (int j = 0; j < 4; j++) acc[f][j] = 0.f;

#pragma unroll 4
        for (int ks = 0; ks < 32; ks++) {
            uint32_t a0, a1, a2, a3, b0, b1, b2, b3;
            ldsm4(a0, a1, a2, a3, addrA0 + ks * 32);
            ldsm4(b0, b1, b2, b3, addrB0 + ks * 32);
            mma16816(acc[0], a0, a1, a2, a3, b0, b1);
            mma16816(acc[1], a0, a1, a2, a3, b2, b3);
        }

        // epilogue for this 32-col chunk
#pragma unroll
        for (int nf = 0; nf < 2; nf++) {
            const int col = nb * 32 + cg * 16 + nf * 8 + tq * 2;
            const float w0 = s_w2q[col], w1 = s_w2q[col + 1];
            const float v0 = s_V[col],   v1 = s_V[col + 1];
            rsum[0] += v0 * fast_tanh(acc[nf][0] + w0) + v1 * fast_tanh(acc[nf][1] + w1);
            rsum[1] += v0 * fast_tanh(acc[nf][2] + w0) + v1 * fast_tanh(acc[nf][3] + w1);
        }
    }

    // quad reduce (tq), then cross-cg reduce via smem
#pragma unroll
    for (int j = 0; j < 2; j++) {
        rsum[j] += __shfl_xor_sync(0xFFFFFFFF, rsum[j], 1);
        rsum[j] += __shfl_xor_sync(0xFFFFFFFF, rsum[j], 2);
    }
    __syncthreads();
    if (tq == 0) {
        s_red[cg * 128 + m0 + gq]     = rsum[0];
        s_red[cg * 128 + m0 + 8 + gq] = rsum[1];
    }
    __syncthreads();
    if (tid < 128) g_u[row0 + tid] = s_red[tid] + s_red[128 + tid];
}

// ==================== kernel 4: masked softmax + exact-fp32 argmax + gather ====================
__global__ void __launch_bounds__(256)
tail_kernel(const float* __restrict__ value, const float* __restrict__ W1,
            const int* __restrict__ mask, const float* __restrict__ Vvec,
            float* __restrict__ out_a, float* __restrict__ out_ctx) {
    int b = blockIdx.x, tid = threadIdx.x;           // 256 threads
    __shared__ float red[256];
    __shared__ float sval[ND];
    __shared__ int   cand[64];
    __shared__ int   ncand;
    __shared__ float best_u;
    __shared__ int   best_t;

    const float* ub = g_u + b * NT;
    const int* mb = mask + b * NT;
    float* ab = out_a + b * NT;

    // pass 1: masked max
    float mx = -3.4e38f;
    for (int t = tid; t < NT; t += 256) {
        float um = ub[t] + (mb[t] ? 0.f : -1e20f);
        mx = fmaxf(mx, um);
    }
    red[tid] = mx; __syncthreads();
    for (int s = 128; s > 0; s >>= 1) { if (tid < s) red[tid] = fmaxf(red[tid], red[tid + s]); __syncthreads(); }
    mx = red[0];
    if (tid == 0) { ncand = 0; best_u = -3.4e38f; best_t = 0; }
    __syncthreads();

    // pass 2: exp + sum + candidate collection (fp16 GEMM abs error << 0.05)
    float sum = 0.f;
    for (int t = tid; t < NT; t += 256) {
        float um = ub[t] + (mb[t] ? 0.f : -1e20f);
        float e = expf(um - mx);
        ab[t] = e;
        sum += e;
        if (um > mx - 0.05f) {
            int p = atomicAdd(&ncand, 1);
            if (p < 64) cand[p] = t;
        }
    }
    red[tid] = sum; __syncthreads();
    for (int s = 128; s > 0; s >>= 1) { if (tid < s) red[tid] += red[tid + s]; __syncthreads(); }
    float inv = 1.0f / red[0];
    __syncthreads();
    for (int t = tid; t < NT; t += 256) ab[t] *= inv;

    // exact-fp32 re-score of candidates
    int nc = min(ncand, 64);
    for (int ci = 0; ci < nc; ci++) {
        int t = cand[ci];
        for (int d = tid; d < ND; d += 256)
            sval[d] = value[((size_t)b * NT + t) * ND + d];
        __syncthreads();
        float p = 0.f;
        for (int n = tid; n < NU; n += 256) {
            float s1 = 0.f;
#pragma unroll 8
            for (int d = 0; d < ND; d++) s1 += sval[d] * W1[(size_t)d * NU + n];
            p += Vvec[n] * tanhf(s1 + g_w2q[b * NU + n]);
        }
        red[tid] = p; __syncthreads();
        for (int s = 128; s > 0; s >>= 1) { if (tid < s) red[tid] += red[tid + s]; __syncthreads(); }
        if (tid == 0) {
            float ue = red[0];
            if (ue > best_u || (ue == best_u && t < best_t)) { best_u = ue; best_t = t; }
        }
        __syncthreads();
    }

    int tb = best_t;
    for (int d = tid; d < ND; d += 256)
        out_ctx[b * ND + d] = value[((size_t)b * NT + tb) * ND + d];
}

// ==================== launch ====================
extern "C" void kernel_launch(void* const* d_in, const int* in_sizes, int n_in,
                              void* d_out, int out_size) {
    const float* value = (const float*)d_in[0];   // [32, 2048, 512]
    const float* query = (const float*)d_in[1];   // [32, 512]
    const int*   mask  = (const int*)d_in[2];     // [32, 2048]
    const float* W1    = (const float*)d_in[3];   // [512, 512]
    const float* W2    = (const float*)d_in[4];   // [512, 512]
    const float* Vv    = (const float*)d_in[5];   // [512]

    float* out     = (float*)d_out;
    float* out_ctx = out;                         // context [32, 512] first
    float* out_a   = out + NBATCH * ND;           // then a [32, 2048]

    cudaFuncSetAttribute(attn_main, cudaFuncAttributeMaxDynamicSharedMemorySize, SMEM_BYTES);

    prep_w1t<<<dim3(NU / 32, ND / 32), dim3(32, 8)>>>(W1);
    prep_w2q<<<NBATCH, 512>>>(query, W2);
    attn_main<<<(NBATCH * NT) / 128, 512, SMEM_BYTES>>>(value, Vv);
    tail_kernel<<<NBATCH, 256>>>(value, W1, mask, Vv, out_a, out_ctx);
}

// round 8
// speedup vs baseline: 1.5468x; 1.4931x over previous
#include <cuda_runtime.h>
#include <cuda_fp16.h>
#include <cstdint>

// Problem dims
#define NBATCH 32
#define NT     2048
#define ND     512
#define NU     512

#define LDA  520    // smem row stride in fp16 elems (1040B: 16B-aligned, conflict-free)
#define BCH  32     // B n-chunk rows
#define NBCH 16     // number of n-chunks (16*32 = 512)
#define BUFB (BCH * LDA * 2)   // 33280 B per B buffer
#define MAXC 16     // max argmax candidates per batch

// ---------------- device scratch (no allocs allowed) ----------------
__device__ float              g_u[NBATCH * NT];    // raw scores u[b,t] (pre-mask)
__device__ __half             g_w1t[NU * ND];      // W1 transposed [n][k] fp16
__device__ float              g_w2q[NBATCH * NU];  // query @ W2
__device__ int                g_cand[NBATCH * MAXC];
__device__ int                g_ncand[NBATCH];
__device__ unsigned long long g_best[NBATCH];      // packed (score_key << 32) | (2047 - t)

// ---------------- asm helpers ----------------
__device__ __forceinline__ uint32_t smem_u32(const void* p) {
    uint32_t a;
    asm("{ .reg .u64 t; cvta.to.shared.u64 t, %1; cvt.u32.u64 %0, t; }" : "=r"(a) : "l"(p));
    return a;
}
__device__ __forceinline__ void ldsm4(uint32_t& r0, uint32_t& r1, uint32_t& r2,
                                      uint32_t& r3, uint32_t addr) {
    asm volatile("ldmatrix.sync.aligned.m8n8.x4.shared.b16 {%0,%1,%2,%3}, [%4];"
                 : "=r"(r0), "=r"(r1), "=r"(r2), "=r"(r3) : "r"(addr));
}
__device__ __forceinline__ void cpasync16(uint32_t dst, const void* src) {
    asm volatile("cp.async.cg.shared.global [%0], [%1], 16;" :: "r"(dst), "l"(src));
}
#define CP_COMMIT() asm volatile("cp.async.commit_group;")
#define CP_WAIT0()  asm volatile("cp.async.wait_group 0;")

__device__ __forceinline__ void mma16816(float* c, uint32_t a0, uint32_t a1,
                                         uint32_t a2, uint32_t a3,
                                         uint32_t b0, uint32_t b1) {
    asm volatile(
        "mma.sync.aligned.m16n8k16.row.col.f32.f16.f16.f32 "
        "{%0,%1,%2,%3}, {%4,%5,%6,%7}, {%8,%9}, {%0,%1,%2,%3};\n"
        : "+f"(c[0]), "+f"(c[1]), "+f"(c[2]), "+f"(c[3])
        : "r"(a0), "r"(a1), "r"(a2), "r"(a3), "r"(b0), "r"(b1));
}

__device__ __forceinline__ float fast_tanh(float x) {
    float e = __expf(2.0f * x);
    return 1.0f - __fdividef(2.0f, e + 1.0f);        // inf-safe
}

// sortable key for (maximize score, tie -> lower t)
__device__ __forceinline__ unsigned long long pack_key(float s, int t) {
    uint32_t u = __float_as_uint(s);
    uint32_t m = (u & 0x80000000u) ? ~u : (u | 0x80000000u);
    return ((unsigned long long)m << 32) | (unsigned)(2047 - t);
}

// ---------------- smem layout for attn_main ----------------
#define SM_A     0                          // 128 x LDA fp16 = 133120
#define SM_B     (128 * LDA * 2)            // 2 x 33280 = 66560
#define SM_W2Q   (SM_B + 2 * BUFB)          // 512 f32
#define SM_V     (SM_W2Q + 512 * 4)         // 512 f32
#define SM_RED   (SM_V + 512 * 4)           // 256 f32
#define SMEM_BYTES (SM_RED + 256 * 4)       // 204800

// ==================== kernel 1: W1 transpose + fp16 convert (tiled) ====================
__global__ void prep_w1t(const float* __restrict__ W1) {
    __shared__ float t[32][33];
    int n0 = blockIdx.x * 32, k0 = blockIdx.y * 32;
    for (int i = threadIdx.y; i < 32; i += 8)
        t[i][threadIdx.x] = W1[(size_t)(k0 + i) * NU + n0 + threadIdx.x];
    __syncthreads();
    for (int i = threadIdx.y; i < 32; i += 8)
        g_w1t[(size_t)(n0 + i) * ND + k0 + threadIdx.x] = __float2half_rn(t[threadIdx.x][i]);
}

// ==================== kernel 2: w2q = query @ W2 (fp32 exact) ====================
__global__ void prep_w2q(const float* __restrict__ query, const float* __restrict__ W2) {
    int b = blockIdx.x, tid = threadIdx.x;           // 512 threads
    __shared__ float q[ND];
    q[tid] = query[b * ND + tid];
    __syncthreads();
    float s = 0.f;
#pragma unroll 8
    for (int d = 0; d < ND; d++) s += q[d] * W2[(size_t)d * NU + tid];
    g_w2q[b * NU + tid] = s;
}

// ==================== kernel 3: fused GEMM + tanh + V-dot ====================
// 512 threads = 16 warps: rg = wid&7 (16-row tile), cg = wid>>3 (16-col tile per chunk)
__global__ void __launch_bounds__(512, 1)
attn_main(const float* __restrict__ value, const float* __restrict__ Vvec) {
    extern __shared__ char smem[];
    __half* sA    = reinterpret_cast<__half*>(smem + SM_A);
    float*  s_w2q = reinterpret_cast<float*>(smem + SM_W2Q);
    float*  s_V   = reinterpret_cast<float*>(smem + SM_V);
    float*  s_red = reinterpret_cast<float*>(smem + SM_RED);

    const uint32_t sA_u = smem_u32(smem) + SM_A;
    const uint32_t sB_u = smem_u32(smem) + SM_B;

    const int tid  = threadIdx.x;
    const int wid  = tid >> 5;
    const int lane = tid & 31;
    const int row0 = blockIdx.x * 128;               // global (b*T + t) row
    const int b    = row0 >> 11;

    // ---- prefetch B chunk 0 into buf 0 (cp.async, overlaps A conversion) ----
    {
        const char* bsrc = reinterpret_cast<const char*>(g_w1t);   // chunk 0
        for (int i = tid; i < 2048; i += 512) {       // 32 rows x 64 x 16B
            int r = i >> 6, c16 = i & 63;
            cpasync16(sB_u + r * (LDA * 2) + c16 * 16, bsrc + r * 1024 + c16 * 16);
        }
        CP_COMMIT();
    }

    // ---- stage A: value[row0:row0+128, :] fp32 -> fp16 smem (padded rows) ----
    const float4* vsrc = reinterpret_cast<const float4*>(value + (size_t)row0 * ND);
    for (int i = tid; i < 128 * 128; i += 512) {     // 16384 float4s
        int r = i >> 7, c4 = i & 127;
        float4 v = vsrc[r * 128 + c4];
        __half2 lo = __floats2half2_rn(v.x, v.y);
        __half2 hi = __floats2half2_rn(v.z, v.w);
        uint2 pk;
        pk.x = *reinterpret_cast<uint32_t*>(&lo);
        pk.y = *reinterpret_cast<uint32_t*>(&hi);
        *reinterpret_cast<uint2*>(sA + (size_t)r * LDA + c4 * 4) = pk;
    }
    if (tid < 512) {
        s_w2q[tid] = g_w2q[b * NU + tid];
        s_V[tid]   = Vvec[tid];
    }

    const int rg = wid & 7, cg = wid >> 3;
    const int gq = lane >> 2, tq = lane & 3;
    const int m0 = rg * 16;

    // per-lane ldmatrix base addresses (k0 = 0)
    const int rowA = m0 + (lane & 7) + ((lane >> 3) & 1) * 8;
    const uint32_t addrA0 = sA_u + (uint32_t)(rowA * LDA + (lane >> 4) * 8) * 2;
    const int rowB = cg * 16 + (lane & 7) + ((lane >> 4) & 1) * 8;
    const uint32_t addrB0_rel = (uint32_t)(rowB * LDA + ((lane >> 3) & 1) * 8) * 2;

    float rsum[2] = {0.f, 0.f};                      // rows m0+gq, m0+8+gq

    for (int nb = 0; nb < NBCH; nb++) {
        CP_WAIT0();
        __syncthreads();                             // buf(nb&1) ready; prev compute done
        if (nb + 1 < NBCH) {                         // prefetch next into other buf
            const char* bsrc = reinterpret_cast<const char*>(g_w1t + (size_t)(nb + 1) * BCH * ND);
            uint32_t bufo = ((nb + 1) & 1) * BUFB;
            for (int i = tid; i < 2048; i += 512) {
                int r = i >> 6, c16 = i & 63;
                cpasync16(sB_u + bufo + r * (LDA * 2) + c16 * 16, bsrc + r * 1024 + c16 * 16);
            }
            CP_COMMIT();
        }

        const uint32_t addrB0 = sB_u + (nb & 1) * BUFB + addrB0_rel;
        float acc[2][4];
#pragma unroll
        for (int f = 0; f < 2; f++)
#pragma unroll
            for (int j = 0; j < 4; j++) acc[f][j] = 0.f;

#pragma unroll 8
        for (int ks = 0; ks < 32; ks++) {
            uint32_t a0, a1, a2, a3, b0, b1, b2, b3;
            ldsm4(a0, a1, a2, a3, addrA0 + ks * 32);
            ldsm4(b0, b1, b2, b3, addrB0 + ks * 32);
            mma16816(acc[0], a0, a1, a2, a3, b0, b1);
            mma16816(acc[1], a0, a1, a2, a3, b2, b3);
        }

        // epilogue for this 32-col chunk
#pragma unroll
        for (int nf = 0; nf < 2; nf++) {
            const int col = nb * 32 + cg * 16 + nf * 8 + tq * 2;
            const float w0 = s_w2q[col], w1 = s_w2q[col + 1];
            const float v0 = s_V[col],   v1 = s_V[col + 1];
            rsum[0] += v0 * fast_tanh(acc[nf][0] + w0) + v1 * fast_tanh(acc[nf][1] + w1);
            rsum[1] += v0 * fast_tanh(acc[nf][2] + w0) + v1 * fast_tanh(acc[nf][3] + w1);
        }
    }

    // quad reduce (tq), then cross-cg reduce via smem
#pragma unroll
    for (int j = 0; j < 2; j++) {
        rsum[j] += __shfl_xor_sync(0xFFFFFFFF, rsum[j], 1);
        rsum[j] += __shfl_xor_sync(0xFFFFFFFF, rsum[j], 2);
    }
    __syncthreads();
    if (tq == 0) {
        s_red[cg * 128 + m0 + gq]     = rsum[0];
        s_red[cg * 128 + m0 + 8 + gq] = rsum[1];
    }
    __syncthreads();
    if (tid < 128) g_u[row0 + tid] = s_red[tid] + s_red[128 + tid];
}

// ==================== kernel 4: masked softmax + candidate collection ====================
__global__ void __launch_bounds__(256)
tail1_kernel(const int* __restrict__ mask, float* __restrict__ out_a) {
    int b = blockIdx.x, tid = threadIdx.x;           // 256 threads
    __shared__ float red[256];
    __shared__ int   ncand;

    const float* ub = g_u + b * NT;
    const int* mb = mask + b * NT;
    float* ab = out_a + b * NT;

    // pass 1: masked max
    float mx = -3.4e38f;
    for (int t = tid; t < NT; t += 256) {
        float um = ub[t] + (mb[t] ? 0.f : -1e20f);
        mx = fmaxf(mx, um);
    }
    red[tid] = mx; __syncthreads();
    for (int s = 128; s > 0; s >>= 1) { if (tid < s) red[tid] = fmaxf(red[tid], red[tid + s]); __syncthreads(); }
    mx = red[0];
    if (tid == 0) { ncand = 0; g_best[b] = 0ull; }
    __syncthreads();

    // pass 2: exp + sum + candidate collection (fp16 GEMM u-error ~1e-3 << 0.01)
    float sum = 0.f;
    for (int t = tid; t < NT; t += 256) {
        float um = ub[t] + (mb[t] ? 0.f : -1e20f);
        float e = expf(um - mx);
        ab[t] = e;
        sum += e;
        if (um > mx - 0.01f) {
            int p = atomicAdd(&ncand, 1);
            if (p < MAXC) g_cand[b * MAXC + p] = t;
        }
    }
    red[tid] = sum; __syncthreads();
    for (int s = 128; s > 0; s >>= 1) { if (tid < s) red[tid] += red[tid + s]; __syncthreads(); }
    float inv = 1.0f / red[0];
    __syncthreads();
    for (int t = tid; t < NT; t += 256) ab[t] *= inv;
    if (tid == 0) g_ncand[b] = min(ncand, MAXC);
}

// ==================== kernel 5: exact-fp32 candidate re-score (1 CTA / candidate) ====
__global__ void __launch_bounds__(512)
tail2_kernel(const float* __restrict__ value, const float* __restrict__ W1,
             const float* __restrict__ Vvec) {
    const int b = blockIdx.x, ci = blockIdx.y, tid = threadIdx.x;   // 512 threads
    if (ci >= g_ncand[b]) return;
    const int t = g_cand[b * MAXC + ci];

    __shared__ float sval[ND];
    __shared__ float red[512];

    sval[tid] = value[((size_t)b * NT + t) * ND + tid];
    __syncthreads();

    // thread tid handles n = tid: s1 = sum_d sval[d] * W1[d, n]  (coalesced over n)
    float s1 = 0.f;
#pragma unroll 8
    for (int d = 0; d < ND; d++) s1 += sval[d] * W1[(size_t)d * NU + tid];
    float p = Vvec[tid] * tanhf(s1 + g_w2q[b * NU + tid]);

    red[tid] = p; __syncthreads();
    for (int s = 256; s > 0; s >>= 1) { if (tid < s) red[tid] += red[tid + s]; __syncthreads(); }
    if (tid == 0)
        atomicMax(&g_best[b], pack_key(red[0], t));
}

// ==================== kernel 6: gather context ====================
__global__ void __launch_bounds__(512)
tail3_kernel(const float* __restrict__ value, float* __restrict__ out_ctx) {
    const int b = blockIdx.x, tid = threadIdx.x;     // 512 threads
    const int t = 2047 - (int)(g_best[b] & 0xFFFFFFFFull);
    out_ctx[b * ND + tid] = value[((size_t)b * NT + t) * ND + tid];
}

// ==================== launch ====================
extern "C" void kernel_launch(void* const* d_in, const int* in_sizes, int n_in,
                              void* d_out, int out_size) {
    const float* value = (const float*)d_in[0];   // [32, 2048, 512]
    const float* query = (const float*)d_in[1];   // [32, 512]
    const int*   mask  = (const int*)d_in[2];     // [32, 2048]
    const float* W1    = (const float*)d_in[3];   // [512, 512]
    const float* W2    = (const float*)d_in[4];   // [512, 512]
    const float* Vv    = (const float*)d_in[5];   // [512]

    float* out     = (float*)d_out;
    float* out_ctx = out;                         // context [32, 512] first
    float* out_a   = out + NBATCH * ND;           // then a [32, 2048]

    cudaFuncSetAttribute(attn_main, cudaFuncAttributeMaxDynamicSharedMemorySize, SMEM_BYTES);

    prep_w1t<<<dim3(NU / 32, ND / 32), dim3(32, 8)>>>(W1);
    prep_w2q<<<NBATCH, 512>>>(query, W2);
    attn_main<<<(NBATCH * NT) / 128, 512, SMEM_BYTES>>>(value, Vv);
    tail1_kernel<<<NBATCH, 256>>>(mask, out_a);
    tail2_kernel<<<dim3(NBATCH, MAXC), 512>>>(value, W1, Vv);
    tail3_kernel<<<NBATCH, 512>>>(value, out_ctx);
}

// round 9
// speedup vs baseline: 1.8369x; 1.1875x over previous
#include <cuda_runtime.h>
#include <cuda_fp16.h>
#include <cstdint>

// Problem dims
#define NBATCH 32
#define NT     2048
#define ND     512
#define NU     512

#define LDA  520    // A smem row stride in fp16 (1040B; 260 words mod 32 = 4 -> conflict-free)
#define LDB  72     // B smem row stride in fp16 (144B; 36 words mod 32 = 4 -> conflict-free)
#define BUFB (128 * LDB * 2)   // 18432 B per B buffer (128 n-rows x 64 k)
#define NCH  32     // chunks: 4 n-blocks x 8 k-chunks
#define MAXC 16     // max argmax candidates per batch

// ---------------- device scratch (no allocs allowed) ----------------
__device__ float              g_u[NBATCH * NT];    // raw scores u[b,t] (pre-mask)
__device__ __half             g_w1t[NU * ND];      // W1 transposed [n][k] fp16
__device__ float              g_w2q[NBATCH * NU];  // query @ W2
__device__ int                g_cand[NBATCH * MAXC];
__device__ int                g_ncand[NBATCH];
__device__ unsigned long long g_best[NBATCH];      // packed (score_key << 32) | (2047 - t)

// ---------------- asm helpers ----------------
__device__ __forceinline__ uint32_t smem_u32(const void* p) {
    uint32_t a;
    asm("{ .reg .u64 t; cvta.to.shared.u64 t, %1; cvt.u32.u64 %0, t; }" : "=r"(a) : "l"(p));
    return a;
}
__device__ __forceinline__ void ldsm4(uint32_t& r0, uint32_t& r1, uint32_t& r2,
                                      uint32_t& r3, uint32_t addr) {
    asm volatile("ldmatrix.sync.aligned.m8n8.x4.shared.b16 {%0,%1,%2,%3}, [%4];"
                 : "=r"(r0), "=r"(r1), "=r"(r2), "=r"(r3) : "r"(addr));
}
__device__ __forceinline__ void cpasync16(uint32_t dst, const void* src) {
    asm volatile("cp.async.cg.shared.global [%0], [%1], 16;" :: "r"(dst), "l"(src));
}
#define CP_COMMIT() asm volatile("cp.async.commit_group;")
#define CP_WAIT0()  asm volatile("cp.async.wait_group 0;")

__device__ __forceinline__ void mma16816(float* c, uint32_t a0, uint32_t a1,
                                         uint32_t a2, uint32_t a3,
                                         uint32_t b0, uint32_t b1) {
    asm volatile(
        "mma.sync.aligned.m16n8k16.row.col.f32.f16.f16.f32 "
        "{%0,%1,%2,%3}, {%4,%5,%6,%7}, {%8,%9}, {%0,%1,%2,%3};\n"
        : "+f"(c[0]), "+f"(c[1]), "+f"(c[2]), "+f"(c[3])
        : "r"(a0), "r"(a1), "r"(a2), "r"(a3), "r"(b0), "r"(b1));
}

__device__ __forceinline__ float fast_tanh(float x) {
    float e = __expf(2.0f * x);
    return 1.0f - __fdividef(2.0f, e + 1.0f);        // inf-safe
}

// sortable key for (maximize score, tie -> lower t)
__device__ __forceinline__ unsigned long long pack_key(float s, int t) {
    uint32_t u = __float_as_uint(s);
    uint32_t m = (u & 0x80000000u) ? ~u : (u | 0x80000000u);
    return ((unsigned long long)m << 32) | (unsigned)(2047 - t);
}

// ---------------- smem layout for attn_main ----------------
#define SM_A     0                          // 128 x LDA fp16 = 133120
#define SM_B     (128 * LDA * 2)            // 2 x 18432 = 36864
#define SM_W2Q   (SM_B + 2 * BUFB)          // 512 f32
#define SM_V     (SM_W2Q + 512 * 4)         // 512 f32
#define SM_RED   (SM_V + 512 * 4)           // 512 f32 (4 col-groups x 128 rows)
#define SMEM_BYTES (SM_RED + 512 * 4)       // 176128

// ==================== kernel 1: W1 transpose + fp16 convert (tiled) ====================
__global__ void prep_w1t(const float* __restrict__ W1) {
    __shared__ float t[32][33];
    int n0 = blockIdx.x * 32, k0 = blockIdx.y * 32;
    for (int i = threadIdx.y; i < 32; i += 8)
        t[i][threadIdx.x] = W1[(size_t)(k0 + i) * NU + n0 + threadIdx.x];
    __syncthreads();
    for (int i = threadIdx.y; i < 32; i += 8)
        g_w1t[(size_t)(n0 + i) * ND + k0 + threadIdx.x] = __float2half_rn(t[threadIdx.x][i]);
}

// ==================== kernel 2: w2q = query @ W2 (fp32 exact) ====================
__global__ void prep_w2q(const float* __restrict__ query, const float* __restrict__ W2) {
    int b = blockIdx.x, tid = threadIdx.x;           // 512 threads
    __shared__ float q[ND];
    q[tid] = query[b * ND + tid];
    __syncthreads();
    float s = 0.f;
#pragma unroll 8
    for (int d = 0; d < ND; d++) s += q[d] * W2[(size_t)d * NU + tid];
    g_w2q[b * NU + tid] = s;
}

// ==================== kernel 2b: init best keys (also shifts ncu -s window) ==========
__global__ void init_best() {
    if (threadIdx.x < NBATCH) g_best[threadIdx.x] = 0ull;
}

// ==================== kernel 3: fused GEMM + tanh + V-dot ====================
// 512 threads = 16 warps as 4x4 grid of 32x32 warp tiles over a 128x128 output block.
// B streamed as 32 chunks (4 n-blocks x 8 k-chunks of 128n x 64k), cp.async double-buffered.
__global__ void __launch_bounds__(512, 1)
attn_main(const float* __restrict__ value, const float* __restrict__ Vvec) {
    extern __shared__ char smem[];
    __half* sA    = reinterpret_cast<__half*>(smem + SM_A);
    float*  s_w2q = reinterpret_cast<float*>(smem + SM_W2Q);
    float*  s_V   = reinterpret_cast<float*>(smem + SM_V);
    float*  s_red = reinterpret_cast<float*>(smem + SM_RED);

    const uint32_t sA_u = smem_u32(smem) + SM_A;
    const uint32_t sB_u = smem_u32(smem) + SM_B;

    const int tid  = threadIdx.x;
    const int wid  = tid >> 5;
    const int lane = tid & 31;
    const int row0 = blockIdx.x * 128;               // global (b*T + t) row
    const int b    = row0 >> 11;

    // ---- prefetch B chunk 0 (n-rows 0..127, k 0..63) into buf 0 ----
    {
        const char* bsrc = reinterpret_cast<const char*>(g_w1t);
        for (int i = tid; i < 1024; i += 512) {      // 128 rows x 8 x 16B
            int r = i >> 3, c16 = i & 7;
            cpasync16(sB_u + r * (LDB * 2) + c16 * 16, bsrc + (size_t)r * 1024 + c16 * 16);
        }
        CP_COMMIT();
    }

    // ---- stage A: value[row0:row0+128, :] fp32 -> fp16 smem (padded rows) ----
    const float4* vsrc = reinterpret_cast<const float4*>(value + (size_t)row0 * ND);
    for (int i = tid; i < 128 * 128; i += 512) {     // 16384 float4s
        int r = i >> 7, c4 = i & 127;
        float4 v = vsrc[r * 128 + c4];
        __half2 lo = __floats2half2_rn(v.x, v.y);
        __half2 hi = __floats2half2_rn(v.z, v.w);
        uint2 pk;
        pk.x = *reinterpret_cast<uint32_t*>(&lo);
        pk.y = *reinterpret_cast<uint32_t*>(&hi);
        *reinterpret_cast<uint2*>(sA + (size_t)r * LDA + c4 * 4) = pk;
    }
    if (tid < 512) {
        s_w2q[tid] = g_w2q[b * NU + tid];
        s_V[tid]   = Vvec[tid];
    }

    const int rg  = wid & 3;                         // row group: m0 = rg*32
    const int cgw = wid >> 2;                        // col group: n0w = cgw*32 (within 128-col block)
    const int gq  = lane >> 2, tq = lane & 3;
    const int m0  = rg * 32;
    const int n0w = cgw * 32;

    // per-lane ldmatrix base addresses
    const int rowA = m0 + (lane & 7) + ((lane >> 3) & 1) * 8;
    const uint32_t addrA0 = sA_u + (uint32_t)(rowA * LDA + (lane >> 4) * 8) * 2;
    const int rowB = n0w + (lane & 7) + ((lane >> 4) & 1) * 8;
    const uint32_t addrB0_rel = (uint32_t)(rowB * LDB + ((lane >> 3) & 1) * 8) * 2;

    float rsum[4] = {0.f, 0.f, 0.f, 0.f};            // rows m0 + mi*16 + h*8 + gq

    int ch = 0;
    for (int nc = 0; nc < 4; nc++) {
        float acc[2][4][4];
#pragma unroll
        for (int mi = 0; mi < 2; mi++)
#pragma unroll
            for (int ni = 0; ni < 4; ni++)
#pragma unroll
                for (int j = 0; j < 4; j++) acc[mi][ni][j] = 0.f;

        for (int kc = 0; kc < 8; kc++, ch++) {
            CP_WAIT0();
            __syncthreads();                         // buf(ch&1) ready; buf(other) free
            if (ch + 1 < NCH) {                      // prefetch next chunk
                int nn = (ch + 1) >> 3, kk = (ch + 1) & 7;
                const char* bsrc = reinterpret_cast<const char*>(g_w1t)
                                 + ((size_t)nn * 128 * ND + (size_t)kk * 64) * 2;
                uint32_t bufo = ((ch + 1) & 1) * BUFB;
                for (int i = tid; i < 1024; i += 512) {
                    int r = i >> 3, c16 = i & 7;
                    cpasync16(sB_u + bufo + r * (LDB * 2) + c16 * 16,
                              bsrc + (size_t)r * 1024 + c16 * 16);
                }
                CP_COMMIT();
            }

            const uint32_t aK = addrA0 + kc * 128;   // k offset: kc*64 elems = kc*128 B
            const uint32_t bB = sB_u + (ch & 1) * BUFB + addrB0_rel;

#pragma unroll
            for (int ks = 0; ks < 4; ks++) {
                uint32_t a0, a1, a2, a3, a4, a5, a6, a7;
                uint32_t b0, b1, b2, b3, b4, b5, b6, b7;
                ldsm4(a0, a1, a2, a3, aK + ks * 32);
                ldsm4(a4, a5, a6, a7, aK + 16 * LDA * 2 + ks * 32);
                ldsm4(b0, b1, b2, b3, bB + ks * 32);
                ldsm4(b4, b5, b6, b7, bB + 16 * LDB * 2 + ks * 32);
                mma16816(acc[0][0], a0, a1, a2, a3, b0, b1);
                mma16816(acc[0][1], a0, a1, a2, a3, b2, b3);
                mma16816(acc[0][2], a0, a1, a2, a3, b4, b5);
                mma16816(acc[0][3], a0, a1, a2, a3, b6, b7);
                mma16816(acc[1][0], a4, a5, a6, a7, b0, b1);
                mma16816(acc[1][1], a4, a5, a6, a7, b2, b3);
                mma16816(acc[1][2], a4, a5, a6, a7, b4, b5);
                mma16816(acc[1][3], a4, a5, a6, a7, b6, b7);
            }
        }

        // ---- epilogue for this 128-col block: tanh + V-dot ----
#pragma unroll
        for (int mi = 0; mi < 2; mi++)
#pragma unroll
            for (int ni = 0; ni < 4; ni++) {
                const int col = nc * 128 + n0w + ni * 8 + tq * 2;
                const float w0 = s_w2q[col], w1 = s_w2q[col + 1];
                const float v0 = s_V[col],   v1 = s_V[col + 1];
                const float* c = acc[mi][ni];
                rsum[mi * 2 + 0] += v0 * fast_tanh(c[0] + w0) + v1 * fast_tanh(c[1] + w1);
                rsum[mi * 2 + 1] += v0 * fast_tanh(c[2] + w0) + v1 * fast_tanh(c[3] + w1);
            }
    }

    // quad reduce (tq lanes), then cross-colgroup reduce via smem
#pragma unroll
    for (int j = 0; j < 4; j++) {
        rsum[j] += __shfl_xor_sync(0xFFFFFFFF, rsum[j], 1);
        rsum[j] += __shfl_xor_sync(0xFFFFFFFF, rsum[j], 2);
    }
    __syncthreads();
    if (tq == 0) {
#pragma unroll
        for (int mi = 0; mi < 2; mi++)
#pragma unroll
            for (int h = 0; h < 2; h++)
                s_red[cgw * 128 + m0 + mi * 16 + h * 8 + gq] = rsum[mi * 2 + h];
    }
    __syncthreads();
    if (tid < 128)
        g_u[row0 + tid] = (s_red[tid] + s_red[128 + tid])
                        + (s_red[256 + tid] + s_red[384 + tid]);
}

// ==================== kernel 4: masked softmax + candidate collection ====================
__global__ void __launch_bounds__(256)
tail1_kernel(const int* __restrict__ mask, float* __restrict__ out_a) {
    int b = blockIdx.x, tid = threadIdx.x;           // 256 threads
    __shared__ float red[256];
    __shared__ int   ncand;

    const float* ub = g_u + b * NT;
    const int* mb = mask + b * NT;
    float* ab = out_a + b * NT;

    // pass 1: masked max
    float mx = -3.4e38f;
    for (int t = tid; t < NT; t += 256) {
        float um = ub[t] + (mb[t] ? 0.f : -1e20f);
        mx = fmaxf(mx, um);
    }
    red[tid] = mx; __syncthreads();
    for (int s = 128; s > 0; s >>= 1) { if (tid < s) red[tid] = fmaxf(red[tid], red[tid + s]); __syncthreads(); }
    mx = red[0];
    if (tid == 0) ncand = 0;
    __syncthreads();

    // pass 2: exp + sum + candidate collection (fp16 GEMM u-error ~1e-3 << 0.01)
    float sum = 0.f;
    for (int t = tid; t < NT; t += 256) {
        float um = ub[t] + (mb[t] ? 0.f : -1e20f);
        float e = expf(um - mx);
        ab[t] = e;
        sum += e;
        if (um > mx - 0.01f) {
            int p = atomicAdd(&ncand, 1);
            if (p < MAXC) g_cand[b * MAXC + p] = t;
        }
    }
    red[tid] = sum; __syncthreads();
    for (int s = 128; s > 0; s >>= 1) { if (tid < s) red[tid] += red[tid + s]; __syncthreads(); }
    float inv = 1.0f / red[0];
    __syncthreads();
    for (int t = tid; t < NT; t += 256) ab[t] *= inv;
    if (tid == 0) g_ncand[b] = min(ncand, MAXC);
}

// ==================== kernel 5: exact-fp32 candidate re-score (1 CTA / candidate) ====
__global__ void __launch_bounds__(512)
tail2_kernel(const float* __restrict__ value, const float* __restrict__ W1,
             const float* __restrict__ Vvec) {
    const int b = blockIdx.x, ci = blockIdx.y, tid = threadIdx.x;   // 512 threads
    if (ci >= g_ncand[b]) return;
    const int t = g_cand[b * MAXC + ci];

    __shared__ float sval[ND];
    __shared__ float red[512];

    sval[tid] = value[((size_t)b * NT + t) * ND + tid];
    __syncthreads();

    // thread tid handles n = tid: s1 = sum_d sval[d] * W1[d, n]  (coalesced over n)
    float s1 = 0.f;
#pragma unroll 8
    for (int d = 0; d < ND; d++) s1 += sval[d] * W1[(size_t)d * NU + tid];
    float p = Vvec[tid] * tanhf(s1 + g_w2q[b * NU + tid]);

    red[tid] = p; __syncthreads();
    for (int s = 256; s > 0; s >>= 1) { if (tid < s) red[tid] += red[tid + s]; __syncthreads(); }
    if (tid == 0)
        atomicMax(&g_best[b], pack_key(red[0], t));
}

// ==================== kernel 6: gather context ====================
__global__ void __launch_bounds__(512)
tail3_kernel(const float* __restrict__ value, float* __restrict__ out_ctx) {
    const int b = blockIdx.x, tid = threadIdx.x;     // 512 threads
    const int t = 2047 - (int)(g_best[b] & 0xFFFFFFFFull);
    out_ctx[b * ND + tid] = value[((size_t)b * NT + t) * ND + tid];
}

// ==================== launch ====================
extern "C" void kernel_launch(void* const* d_in, const int* in_sizes, int n_in,
                              void* d_out, int out_size) {
    const float* value = (const float*)d_in[0];   // [32, 2048, 512]
    const float* query = (const float*)d_in[1];   // [32, 512]
    const int*   mask  = (const int*)d_in[2];     // [32, 2048]
    const float* W1    = (const float*)d_in[3];   // [512, 512]
    const float* W2    = (const float*)d_in[4];   // [512, 512]
    const float* Vv    = (const float*)d_in[5];   // [512]

    float* out     = (float*)d_out;
    float* out_ctx = out;                         // context [32, 512] first
    float* out_a   = out + NBATCH * ND;           // then a [32, 2048]

    cudaFuncSetAttribute(attn_main, cudaFuncAttributeMaxDynamicSharedMemorySize, SMEM_BYTES);

    prep_w1t<<<dim3(NU / 32, ND / 32), dim3(32, 8)>>>(W1);
    prep_w2q<<<NBATCH, 512>>>(query, W2);
    init_best<<<1, 32>>>();
    attn_main<<<(NBATCH * NT) / 128, 512, SMEM_BYTES>>>(value, Vv);
    tail1_kernel<<<NBATCH, 256>>>(mask, out_a);
    tail2_kernel<<<dim3(NBATCH, MAXC), 512>>>(value, W1, Vv);
    tail3_kernel<<<NBATCH, 512>>>(value, out_ctx);
}

// round 13
// speedup vs baseline: 2.0191x; 1.0992x over previous
#include <cuda_runtime.h>
#include <cuda_fp16.h>
#include <cstdint>

// Problem dims
#define NBATCH 32
#define NT     2048
#define ND     512
#define NU     512

#define LDA  520    // A smem row stride in fp16 (1040B; 260 words mod 32 = 4 -> conflict-free)
#define LDB  136    // B smem row stride in fp16 (272B; 68 words mod 32 = 4 -> conflict-free)
#define BUFB (128 * LDB * 2)   // 34816 B per B buffer (128 n-rows x 128 k)
#define NCH  16     // chunks: 4 n-blocks x 4 k-chunks (128k each)
#define MAXC 16     // max argmax candidates per batch

// ---------------- device scratch (no allocs allowed) ----------------
__device__ float              g_u[NBATCH * NT];    // raw scores u[b,t] (pre-mask)
__device__ __half             g_w1t[NU * ND];      // W1 transposed [n][k] fp16
__device__ float              g_w2q[NBATCH * NU];  // query @ W2
__device__ int                g_cand[NBATCH * MAXC];
__device__ int                g_ncand[NBATCH];
__device__ unsigned long long g_best[NBATCH];      // packed (score_key << 32) | (2047 - t)

// ---------------- asm helpers ----------------
__device__ __forceinline__ uint32_t smem_u32(const void* p) {
    uint32_t a;
    asm("{ .reg .u64 t; cvta.to.shared.u64 t, %1; cvt.u32.u64 %0, t; }" : "=r"(a) : "l"(p));
    return a;
}
__device__ __forceinline__ void ldsm4(uint32_t& r0, uint32_t& r1, uint32_t& r2,
                                      uint32_t& r3, uint32_t addr) {
    asm volatile("ldmatrix.sync.aligned.m8n8.x4.shared.b16 {%0,%1,%2,%3}, [%4];"
                 : "=r"(r0), "=r"(r1), "=r"(r2), "=r"(r3) : "r"(addr));
}
__device__ __forceinline__ void cpasync16(uint32_t dst, const void* src) {
    asm volatile("cp.async.cg.shared.global [%0], [%1], 16;" :: "r"(dst), "l"(src));
}
#define CP_COMMIT() asm volatile("cp.async.commit_group;")
#define CP_WAIT0()  asm volatile("cp.async.wait_group 0;")

__device__ __forceinline__ void mma16816(float* c, uint32_t a0, uint32_t a1,
                                         uint32_t a2, uint32_t a3,
                                         uint32_t b0, uint32_t b1) {
    asm volatile(
        "mma.sync.aligned.m16n8k16.row.col.f32.f16.f16.f32 "
        "{%0,%1,%2,%3}, {%4,%5,%6,%7}, {%8,%9}, {%0,%1,%2,%3};\n"
        : "+f"(c[0]), "+f"(c[1]), "+f"(c[2]), "+f"(c[3])
        : "r"(a0), "r"(a1), "r"(a2), "r"(a3), "r"(b0), "r"(b1));
}

__device__ __forceinline__ float fast_tanh(float x) {
    float e = __expf(2.0f * x);
    return 1.0f - __fdividef(2.0f, e + 1.0f);        // inf-safe
}

// sortable key for (maximize score, tie -> lower t)
__device__ __forceinline__ unsigned long long pack_key(float s, int t) {
    uint32_t u = __float_as_uint(s);
    uint32_t m = (u & 0x80000000u) ? ~u : (u | 0x80000000u);
    return ((unsigned long long)m << 32) | (unsigned)(2047 - t);
}

// ---------------- smem layout for attn_main ----------------
#define SM_A     0                          // 128 x LDA fp16 = 133120
#define SM_B     (128 * LDA * 2)            // 2 x 34816 = 69632
#define SM_W2Q   (SM_B + 2 * BUFB)          // 512 f32
#define SM_V     (SM_W2Q + 512 * 4)         // 512 f32
#define SM_RED   (SM_V + 512 * 4)           // 512 f32 (4 col-groups x 128 rows)
#define SMEM_BYTES (SM_RED + 512 * 4)       // 208896

// ==================== kernel 1: W1 transpose + fp16 convert (tiled) ====================
__global__ void prep_w1t(const float* __restrict__ W1) {
    __shared__ float t[32][33];
    int n0 = blockIdx.x * 32, k0 = blockIdx.y * 32;
    for (int i = threadIdx.y; i < 32; i += 8)
        t[i][threadIdx.x] = W1[(size_t)(k0 + i) * NU + n0 + threadIdx.x];
    __syncthreads();
    for (int i = threadIdx.y; i < 32; i += 8)
        g_w1t[(size_t)(n0 + i) * ND + k0 + threadIdx.x] = __float2half_rn(t[threadIdx.x][i]);
}

// ==================== kernel 2: w2q = query @ W2 (fp32 exact) ====================
__global__ void prep_w2q(const float* __restrict__ query, const float* __restrict__ W2) {
    int b = blockIdx.x, tid = threadIdx.x;           // 512 threads
    __shared__ float q[ND];
    q[tid] = query[b * ND + tid];
    __syncthreads();
    float s = 0.f;
#pragma unroll 8
    for (int d = 0; d < ND; d++) s += q[d] * W2[(size_t)d * NU + tid];
    g_w2q[b * NU + tid] = s;
}

// ==================== kernel 2b: init best keys ====================
__global__ void init_best() {
    if (threadIdx.x < NBATCH) g_best[threadIdx.x] = 0ull;
}

// ==================== kernel 3: fused GEMM + tanh + V-dot ====================
// 512 threads = 16 warps as 4x4 grid of 32x32 warp tiles over a 128x128 output block.
// B streamed as 16 chunks (4 n-blocks x 4 k-chunks of 128n x 128k), cp.async double-buffered.
// A (value fp32->fp16) staged in 4 k-chunks, pipelined into the first n-block's k loop.
__global__ void __launch_bounds__(512, 1)
attn_main(const float* __restrict__ value, const float* __restrict__ Vvec) {
    extern __shared__ char smem[];
    __half* sA    = reinterpret_cast<__half*>(smem + SM_A);
    float*  s_w2q = reinterpret_cast<float*>(smem + SM_W2Q);
    float*  s_V   = reinterpret_cast<float*>(smem + SM_V);
    float*  s_red = reinterpret_cast<float*>(smem + SM_RED);

    const uint32_t sA_u = smem_u32(smem) + SM_A;
    const uint32_t sB_u = smem_u32(smem) + SM_B;

    const int tid  = threadIdx.x;
    const int wid  = tid >> 5;
    const int lane = tid & 31;
    const int row0 = blockIdx.x * 128;               // global (b*T + t) row
    const int b    = row0 >> 11;

    const float4* vsrc = reinterpret_cast<const float4*>(value + (size_t)row0 * ND);

    // ---- prefetch B chunk 0 (n 0..127, k 0..127) into buf 0 ----
    {
        const char* bsrc = reinterpret_cast<const char*>(g_w1t);
#pragma unroll
        for (int j = 0; j < 4; j++) {
            int i = tid + j * 512;                   // 0..2047: 128 rows x 16 x 16B
            int r = i >> 4, c16 = i & 15;
            cpasync16(sB_u + r * (LDB * 2) + c16 * 16, bsrc + (size_t)r * 1024 + c16 * 16);
        }
        CP_COMMIT();
    }

    // ---- A chunk 0 (k 0..127): LDG fp32 -> regs ----
    float4 apre[8];
#pragma unroll
    for (int j = 0; j < 8; j++) {
        int i = tid + j * 512;                       // 0..4095: 128 rows x 32 float4
        int r = i >> 5, c4 = i & 31;
        apre[j] = vsrc[r * 128 + c4];
    }
    // w2q row + V
    s_w2q[tid] = g_w2q[b * NU + tid];
    s_V[tid]   = Vvec[tid];
    // convert + STS A chunk 0
#pragma unroll
    for (int j = 0; j < 8; j++) {
        int i = tid + j * 512;
        int r = i >> 5, c4 = i & 31;
        __half2 lo = __floats2half2_rn(apre[j].x, apre[j].y);
        __half2 hi = __floats2half2_rn(apre[j].z, apre[j].w);
        uint2 pk;
        pk.x = *reinterpret_cast<uint32_t*>(&lo);
        pk.y = *reinterpret_cast<uint32_t*>(&hi);
        *reinterpret_cast<uint2*>(sA + (size_t)r * LDA + c4 * 4) = pk;
    }
    CP_WAIT0();
    __syncthreads();                                 // B0 + A0 ready

    const int rg  = wid & 3;                         // row group: m0 = rg*32
    const int cgw = wid >> 2;                        // col group: n0w = cgw*32
    const int gq  = lane >> 2, tq = lane & 3;
    const int m0  = rg * 32;
    const int n0w = cgw * 32;

    const int rowA = m0 + (lane & 7) + ((lane >> 3) & 1) * 8;
    const uint32_t addrA0 = sA_u + (uint32_t)(rowA * LDA + (lane >> 4) * 8) * 2;
    const int rowB = n0w + (lane & 7) + ((lane >> 4) & 1) * 8;
    const uint32_t addrB0_rel = (uint32_t)(rowB * LDB + ((lane >> 3) & 1) * 8) * 2;

    float rsum[4] = {0.f, 0.f, 0.f, 0.f};
    float acc[2][4][4];

    for (int ch = 0; ch < NCH; ch++) {
        const int nc = ch >> 2, kc = ch & 3;
        if (kc == 0) {
#pragma unroll
            for (int mi = 0; mi < 2; mi++)
#pragma unroll
                for (int ni = 0; ni < 4; ni++)
#pragma unroll
                    for (int j = 0; j < 4; j++) acc[mi][ni][j] = 0.f;
        }

        // prefetch B chunk ch+1
        if (ch + 1 < NCH) {
            int nn = (ch + 1) >> 2, kk = (ch + 1) & 3;
            const char* bsrc = reinterpret_cast<const char*>(g_w1t)
                             + (size_t)nn * 128 * ND * 2 + (size_t)kk * 256;
            uint32_t bufo = ((ch + 1) & 1) * BUFB;
#pragma unroll
            for (int j = 0; j < 4; j++) {
                int i = tid + j * 512;
                int r = i >> 4, c16 = i & 15;
                cpasync16(sB_u + bufo + r * (LDB * 2) + c16 * 16,
                          bsrc + (size_t)r * 1024 + c16 * 16);
            }
            CP_COMMIT();
        }

        // prefetch A chunk ch+1 (fp32 -> regs) during compute of chunks 0..2
        if (ch < 3) {
            const int c = ch + 1;
#pragma unroll
            for (int j = 0; j < 8; j++) {
                int i = tid + j * 512;
                int r = i >> 5, c4 = i & 31;
                apre[j] = vsrc[r * 128 + c * 32 + c4];
            }
        }

        // ---- compute chunk (nc, kc): 8 k-steps of 16 ----
        const uint32_t aK = addrA0 + kc * 256;       // kc*128 fp16 = 256B
        const uint32_t bB = sB_u + (ch & 1) * BUFB + addrB0_rel;
#pragma unroll
        for (int ks = 0; ks < 8; ks++) {
            uint32_t a0, a1, a2, a3, a4, a5, a6, a7;
            uint32_t b0, b1, b2, b3, b4, b5, b6, b7;
            ldsm4(a0, a1, a2, a3, aK + ks * 32);
            ldsm4(a4, a5, a6, a7, aK + 16 * LDA * 2 + ks * 32);
            ldsm4(b0, b1, b2, b3, bB + ks * 32);
            ldsm4(b4, b5, b6, b7, bB + 16 * LDB * 2 + ks * 32);
            mma16816(acc[0][0], a0, a1, a2, a3, b0, b1);
            mma16816(acc[0][1], a0, a1, a2, a3, b2, b3);
            mma16816(acc[0][2], a0, a1, a2, a3, b4, b5);
            mma16816(acc[0][3], a0, a1, a2, a3, b6, b7);
            mma16816(acc[1][0], a4, a5, a6, a7, b0, b1);
            mma16816(acc[1][1], a4, a5, a6, a7, b2, b3);
            mma16816(acc[1][2], a4, a5, a6, a7, b4, b5);
            mma16816(acc[1][3], a4, a5, a6, a7, b6, b7);
        }

        // epilogue for completed 128-col block
        if (kc == 3) {
#pragma unroll
            for (int mi = 0; mi < 2; mi++)
#pragma unroll
                for (int ni = 0; ni < 4; ni++) {
                    const int col = nc * 128 + n0w + ni * 8 + tq * 2;
                    const float w0 = s_w2q[col], w1 = s_w2q[col + 1];
                    const float v0 = s_V[col],   v1 = s_V[col + 1];
                    const float* c = acc[mi][ni];
                    rsum[mi * 2 + 0] += v0 * fast_tanh(c[0] + w0) + v1 * fast_tanh(c[1] + w1);
                    rsum[mi * 2 + 1] += v0 * fast_tanh(c[2] + w0) + v1 * fast_tanh(c[3] + w1);
                }
        }

        if (ch + 1 < NCH) {
            CP_WAIT0();                              // B chunk ch+1 landed
            if (ch < 3) {                            // STS A chunk ch+1 (disjoint k-cols)
                const int c = ch + 1;
#pragma unroll
                for (int j = 0; j < 8; j++) {
                    int i = tid + j * 512;
                    int r = i >> 5, c4 = i & 31;
                    __half2 lo = __floats2half2_rn(apre[j].x, apre[j].y);
                    __half2 hi = __floats2half2_rn(apre[j].z, apre[j].w);
                    uint2 pk;
                    pk.x = *reinterpret_cast<uint32_t*>(&lo);
                    pk.y = *reinterpret_cast<uint32_t*>(&hi);
                    *reinterpret_cast<uint2*>(sA + (size_t)r * LDA + c * 128 + c4 * 4) = pk;
                }
            }
            __syncthreads();
        }
    }

    // quad reduce (tq lanes), then cross-colgroup reduce via smem
#pragma unroll
    for (int j = 0; j < 4; j++) {
        rsum[j] += __shfl_xor_sync(0xFFFFFFFF, rsum[j], 1);
        rsum[j] += __shfl_xor_sync(0xFFFFFFFF, rsum[j], 2);
    }
    __syncthreads();
    if (tq == 0) {
#pragma unroll
        for (int mi = 0; mi < 2; mi++)
#pragma unroll
            for (int h = 0; h < 2; h++)
                s_red[cgw * 128 + m0 + mi * 16 + h * 8 + gq] = rsum[mi * 2 + h];
    }
    __syncthreads();
    if (tid < 128)
        g_u[row0 + tid] = (s_red[tid] + s_red[128 + tid])
                        + (s_red[256 + tid] + s_red[384 + tid]);
}

// ==================== kernel 4: masked softmax + candidate collection ====================
__global__ void __launch_bounds__(256)
tail1_kernel(const int* __restrict__ mask, float* __restrict__ out_a) {
    int b = blockIdx.x, tid = threadIdx.x;           // 256 threads
    __shared__ float red[256];
    __shared__ int   ncand;

    const float* ub = g_u + b * NT;
    const int* mb = mask + b * NT;
    float* ab = out_a + b * NT;

    float mx = -3.4e38f;
    for (int t = tid; t < NT; t += 256) {
        float um = ub[t] + (mb[t] ? 0.f : -1e20f);
        mx = fmaxf(mx, um);
    }
    red[tid] = mx; __syncthreads();
    for (int s = 128; s > 0; s >>= 1) { if (tid < s) red[tid] = fmaxf(red[tid], red[tid + s]); __syncthreads(); }
    mx = red[0];
    if (tid == 0) ncand = 0;
    __syncthreads();

    float sum = 0.f;
    for (int t = tid; t < NT; t += 256) {
        float um = ub[t] + (mb[t] ? 0.f : -1e20f);
        float e = expf(um - mx);
        ab[t] = e;
        sum += e;
        if (um > mx - 0.01f) {                       // fp16 GEMM u-error ~1e-3 << 0.01
            int p = atomicAdd(&ncand, 1);
            if (p < MAXC) g_cand[b * MAXC + p] = t;
        }
    }
    red[tid] = sum; __syncthreads();
    for (int s = 128; s > 0; s >>= 1) { if (tid < s) red[tid] += red[tid + s]; __syncthreads(); }
    float inv = 1.0f / red[0];
    __syncthreads();
    for (int t = tid; t < NT; t += 256) ab[t] *= inv;
    if (tid == 0) g_ncand[b] = min(ncand, MAXC);
}

// ==================== kernel 5: exact-fp32 candidate re-score (1 CTA / candidate) ====
__global__ void __launch_bounds__(512)
tail2_kernel(const float* __restrict__ value, const float* __restrict__ W1,
             const float* __restrict__ Vvec) {
    const int b = blockIdx.x, ci = blockIdx.y, tid = threadIdx.x;   // 512 threads
    if (ci >= g_ncand[b]) return;
    const int t = g_cand[b * MAXC + ci];

    __shared__ float sval[ND];
    __shared__ float red[512];

    sval[tid] = value[((size_t)b * NT + t) * ND + tid];
    __syncthreads();

    float s1 = 0.f;
#pragma unroll 8
    for (int d = 0; d < ND; d++) s1 += sval[d] * W1[(size_t)d * NU + tid];
    float p = Vvec[tid] * tanhf(s1 + g_w2q[b * NU + tid]);

    red[tid] = p; __syncthreads();
    for (int s = 256; s > 0; s >>= 1) { if (tid < s) red[tid] += red[tid + s]; __syncthreads(); }
    if (tid == 0)
        atomicMax(&g_best[b], pack_key(red[0], t));
}

// ==================== kernel 6: gather context ====================
__global__ void __launch_bounds__(512)
tail3_kernel(const float* __restrict__ value, float* __restrict__ out_ctx) {
    const int b = blockIdx.x, tid = threadIdx.x;     // 512 threads
    const int t = 2047 - (int)(g_best[b] & 0xFFFFFFFFull);
    out_ctx[b * ND + tid] = value[((size_t)b * NT + t) * ND + tid];
}

// ==================== launch ====================
extern "C" void kernel_launch(void* const* d_in, const int* in_sizes, int n_in,
                              void* d_out, int out_size) {
    const float* value = (const float*)d_in[0];   // [32, 2048, 512]
    const float* query = (const float*)d_in[1];   // [32, 512]
    const int*   mask  = (const int*)d_in[2];     // [32, 2048]
    const float* W1    = (const float*)d_in[3];   // [512, 512]
    const float* W2    = (const float*)d_in[4];   // [512, 512]
    const float* Vv    = (const float*)d_in[5];   // [512]

    float* out     = (float*)d_out;
    float* out_ctx = out;                         // context [32, 512] first
    float* out_a   = out + NBATCH * ND;           // then a [32, 2048]

    cudaFuncSetAttribute(attn_main, cudaFuncAttributeMaxDynamicSharedMemorySize, SMEM_BYTES);

    prep_w1t<<<dim3(NU / 32, ND / 32), dim3(32, 8)>>>(W1);          // idx 0
    prep_w2q<<<NBATCH, 512>>>(query, W2);                            // idx 1
    init_best<<<1, 32>>>();                                          // idx 2
    attn_main<<<(NBATCH * NT) / 128, 512, SMEM_BYTES>>>(value, Vv);  // idx 3 (profiled)
    tail1_kernel<<<NBATCH, 256>>>(mask, out_a);
    tail2_kernel<<<dim3(NBATCH, MAXC), 512>>>(value, W1, Vv);
    tail3_kernel<<<NBATCH, 512>>>(value, out_ctx);
}

// round 16
// speedup vs baseline: 2.1337x; 1.0568x over previous
#include <cuda_runtime.h>
#include <cuda_fp16.h>
#include <cstdint>

// Problem dims
#define NBATCH 32
#define NT     2048
#define ND     512
#define NU     512

#define LDA  520    // A smem row stride in fp16 (1040B; 260 words mod 32 = 4 -> conflict-free)
#define LDB  72     // B smem row stride in fp16 (144B; 36 words mod 32 = 4 -> conflict-free)
#define BUFB (128 * LDB * 2)   // 18432 B per B buffer (128 n-rows x 64 k)
#define NCH  32     // chunks: 4 n-blocks x 8 k-chunks (64k each)
#define MAXC 16     // max argmax candidates per batch

// ---------------- device scratch (no allocs allowed) ----------------
__device__ float              g_u[NBATCH * NT];    // raw scores u[b,t] (pre-mask)
__device__ __half             g_w1t[NU * ND];      // W1 transposed [n][k] fp16
__device__ float              g_w2q[NBATCH * NU];  // query @ W2
__device__ int                g_cand[NBATCH * MAXC];
__device__ int                g_ncand[NBATCH];
__device__ unsigned long long g_best[NBATCH];      // packed (score_key << 32) | (2047 - t)

// ---------------- asm helpers ----------------
__device__ __forceinline__ uint32_t smem_u32(const void* p) {
    uint32_t a;
    asm("{ .reg .u64 t; cvta.to.shared.u64 t, %1; cvt.u32.u64 %0, t; }" : "=r"(a) : "l"(p));
    return a;
}
__device__ __forceinline__ void ldsm4(uint32_t& r0, uint32_t& r1, uint32_t& r2,
                                      uint32_t& r3, uint32_t addr) {
    asm volatile("ldmatrix.sync.aligned.m8n8.x4.shared.b16 {%0,%1,%2,%3}, [%4];"
                 : "=r"(r0), "=r"(r1), "=r"(r2), "=r"(r3) : "r"(addr));
}
__device__ __forceinline__ void cpasync16(uint32_t dst, const void* src) {
    asm volatile("cp.async.cg.shared.global [%0], [%1], 16;" :: "r"(dst), "l"(src));
}
#define CP_COMMIT() asm volatile("cp.async.commit_group;")
#define CP_WAIT0()  asm volatile("cp.async.wait_group 0;")

__device__ __forceinline__ void mma16816(float* c, uint32_t a0, uint32_t a1,
                                         uint32_t a2, uint32_t a3,
                                         uint32_t b0, uint32_t b1) {
    asm volatile(
        "mma.sync.aligned.m16n8k16.row.col.f32.f16.f16.f32 "
        "{%0,%1,%2,%3}, {%4,%5,%6,%7}, {%8,%9}, {%0,%1,%2,%3};\n"
        : "+f"(c[0]), "+f"(c[1]), "+f"(c[2]), "+f"(c[3])
        : "r"(a0), "r"(a1), "r"(a2), "r"(a3), "r"(b0), "r"(b1));
}

// HW tanh (sm_75+): single MUFU op, abs err ~1e-4 — inside error budget
__device__ __forceinline__ float tanh_approx(float x) {
    float y;
    asm("tanh.approx.f32 %0, %1;" : "=f"(y) : "f"(x));
    return y;
}

// sortable key for (maximize score, tie -> lower t)
__device__ __forceinline__ unsigned long long pack_key(float s, int t) {
    uint32_t u = __float_as_uint(s);
    uint32_t m = (u & 0x80000000u) ? ~u : (u | 0x80000000u);
    return ((unsigned long long)m << 32) | (unsigned)(2047 - t);
}

// ---------------- smem layout for attn_main (64-row CTA) ----------------
#define SM_A     0                          // 64 x LDA fp16 = 66560
#define SM_B     (64 * LDA * 2)             // 2 x 18432 = 36864
#define SM_W2Q   (SM_B + 2 * BUFB)          // 512 f32
#define SM_V     (SM_W2Q + 512 * 4)         // 512 f32
#define SM_RED   (SM_V + 512 * 4)           // 256 f32 (4 col-groups x 64 rows)
#define SMEM_BYTES (SM_RED + 256 * 4)       // 108544 -> 2 CTAs/SM fit

// ==================== kernel 1: W1 transpose + fp16 convert (tiled) ====================
__global__ void prep_w1t(const float* __restrict__ W1) {
    __shared__ float t[32][33];
    int n0 = blockIdx.x * 32, k0 = blockIdx.y * 32;
    for (int i = threadIdx.y; i < 32; i += 8)
        t[i][threadIdx.x] = W1[(size_t)(k0 + i) * NU + n0 + threadIdx.x];
    __syncthreads();
    for (int i = threadIdx.y; i < 32; i += 8)
        g_w1t[(size_t)(n0 + i) * ND + k0 + threadIdx.x] = __float2half_rn(t[threadIdx.x][i]);
}

// ==================== kernel 2: w2q = query @ W2 (fp32 exact) ====================
__global__ void prep_w2q(const float* __restrict__ query, const float* __restrict__ W2) {
    int b = blockIdx.x, tid = threadIdx.x;           // 512 threads
    __shared__ float q[ND];
    q[tid] = query[b * ND + tid];
    __syncthreads();
    float s = 0.f;
#pragma unroll 8
    for (int d = 0; d < ND; d++) s += q[d] * W2[(size_t)d * NU + tid];
    g_w2q[b * NU + tid] = s;
}

// ==================== kernel 2b: init best keys ====================
__global__ void init_best() {
    if (threadIdx.x < NBATCH) g_best[threadIdx.x] = 0ull;
}

// ==================== kernel 3: fused GEMM + tanh + V-dot ====================
// 64-row CTAs, 256 threads = 8 warps as 2x4 grid of 32x32 warp tiles; 2 CTAs/SM.
// B streamed as 32 chunks (4 n-blocks x 8 k-chunks of 128n x 64k), cp.async double-buffered.
__global__ void __launch_bounds__(256, 2)
attn_main(const float* __restrict__ value, const float* __restrict__ Vvec) {
    extern __shared__ char smem[];
    __half* sA    = reinterpret_cast<__half*>(smem + SM_A);
    float*  s_w2q = reinterpret_cast<float*>(smem + SM_W2Q);
    float*  s_V   = reinterpret_cast<float*>(smem + SM_V);
    float*  s_red = reinterpret_cast<float*>(smem + SM_RED);

    const uint32_t sA_u = smem_u32(smem) + SM_A;
    const uint32_t sB_u = smem_u32(smem) + SM_B;

    const int tid  = threadIdx.x;
    const int wid  = tid >> 5;
    const int lane = tid & 31;
    const int row0 = blockIdx.x * 64;                // global (b*T + t) row
    const int b    = row0 >> 11;

    // ---- prefetch B chunk 0 (n 0..127, k 0..63) into buf 0 ----
    {
        const char* bsrc = reinterpret_cast<const char*>(g_w1t);
#pragma unroll
        for (int j = 0; j < 4; j++) {
            int i = tid + j * 256;                   // 0..1023: 128 rows x 8 x 16B
            int r = i >> 3, c16 = i & 7;
            cpasync16(sB_u + r * (LDB * 2) + c16 * 16, bsrc + (size_t)r * 1024 + c16 * 16);
        }
        CP_COMMIT();
    }

    // ---- stage A: value[row0:row0+64, :] fp32 -> fp16 smem (padded rows) ----
    const float4* vsrc = reinterpret_cast<const float4*>(value + (size_t)row0 * ND);
    for (int i = tid; i < 64 * 128; i += 256) {      // 8192 float4s
        int r = i >> 7, c4 = i & 127;
        float4 v = vsrc[r * 128 + c4];
        __half2 lo = __floats2half2_rn(v.x, v.y);
        __half2 hi = __floats2half2_rn(v.z, v.w);
        uint2 pk;
        pk.x = *reinterpret_cast<uint32_t*>(&lo);
        pk.y = *reinterpret_cast<uint32_t*>(&hi);
        *reinterpret_cast<uint2*>(sA + (size_t)r * LDA + c4 * 4) = pk;
    }
    for (int i = tid; i < 512; i += 256) {
        s_w2q[i] = g_w2q[b * NU + i];
        s_V[i]   = Vvec[i];
    }
    CP_WAIT0();
    __syncthreads();                                 // B0 + A ready

    const int rg  = wid & 1;                         // row group: m0 = rg*32
    const int cgw = wid >> 1;                        // col group: n0w = cgw*32
    const int gq  = lane >> 2, tq = lane & 3;
    const int m0  = rg * 32;
    const int n0w = cgw * 32;

    const int rowA = m0 + (lane & 7) + ((lane >> 3) & 1) * 8;
    const uint32_t addrA0 = sA_u + (uint32_t)(rowA * LDA + (lane >> 4) * 8) * 2;
    const int rowB = n0w + (lane & 7) + ((lane >> 4) & 1) * 8;
    const uint32_t addrB0_rel = (uint32_t)(rowB * LDB + ((lane >> 3) & 1) * 8) * 2;

    float rsum[4] = {0.f, 0.f, 0.f, 0.f};
    float acc[2][4][4];

    for (int ch = 0; ch < NCH; ch++) {
        const int nc = ch >> 3, kc = ch & 7;
        if (kc == 0) {
#pragma unroll
            for (int mi = 0; mi < 2; mi++)
#pragma unroll
                for (int ni = 0; ni < 4; ni++)
#pragma unroll
                    for (int j = 0; j < 4; j++) acc[mi][ni][j] = 0.f;
        }

        // prefetch B chunk ch+1 into the other buffer
        if (ch + 1 < NCH) {
            int nn = (ch + 1) >> 3, kk = (ch + 1) & 7;
            const char* bsrc = reinterpret_cast<const char*>(g_w1t)
                             + (size_t)nn * 131072 + (size_t)kk * 128;
            uint32_t bufo = ((ch + 1) & 1) * BUFB;
#pragma unroll
            for (int j = 0; j < 4; j++) {
                int i = tid + j * 256;
                int r = i >> 3, c16 = i & 7;
                cpasync16(sB_u + bufo + r * (LDB * 2) + c16 * 16,
                          bsrc + (size_t)r * 1024 + c16 * 16);
            }
            CP_COMMIT();
        }

        // ---- compute chunk (nc, kc): 4 k-steps of 16 ----
        const uint32_t aK = addrA0 + kc * 128;       // kc*64 fp16 = 128B
        const uint32_t bB = sB_u + (ch & 1) * BUFB + addrB0_rel;
#pragma unroll
        for (int ks = 0; ks < 4; ks++) {
            uint32_t a0, a1, a2, a3, a4, a5, a6, a7;
            uint32_t b0, b1, b2, b3, b4, b5, b6, b7;
            ldsm4(a0, a1, a2, a3, aK + ks * 32);
            ldsm4(a4, a5, a6, a7, aK + 16 * LDA * 2 + ks * 32);
            ldsm4(b0, b1, b2, b3, bB + ks * 32);
            ldsm4(b4, b5, b6, b7, bB + 16 * LDB * 2 + ks * 32);
            mma16816(acc[0][0], a0, a1, a2, a3, b0, b1);
            mma16816(acc[0][1], a0, a1, a2, a3, b2, b3);
            mma16816(acc[0][2], a0, a1, a2, a3, b4, b5);
            mma16816(acc[0][3], a0, a1, a2, a3, b6, b7);
            mma16816(acc[1][0], a4, a5, a6, a7, b0, b1);
            mma16816(acc[1][1], a4, a5, a6, a7, b2, b3);
            mma16816(acc[1][2], a4, a5, a6, a7, b4, b5);
            mma16816(acc[1][3], a4, a5, a6, a7, b6, b7);
        }

        // epilogue for completed 128-col block
        if (kc == 7) {
#pragma unroll
            for (int mi = 0; mi < 2; mi++)
#pragma unroll
                for (int ni = 0; ni < 4; ni++) {
                    const int col = nc * 128 + n0w + ni * 8 + tq * 2;
                    const float w0 = s_w2q[col], w1 = s_w2q[col + 1];
                    const float v0 = s_V[col],   v1 = s_V[col + 1];
                    const float* c = acc[mi][ni];
                    rsum[mi * 2 + 0] += v0 * tanh_approx(c[0] + w0) + v1 * tanh_approx(c[1] + w1);
                    rsum[mi * 2 + 1] += v0 * tanh_approx(c[2] + w0) + v1 * tanh_approx(c[3] + w1);
                }
        }

        if (ch + 1 < NCH) {
            CP_WAIT0();                              // B chunk ch+1 landed
            __syncthreads();
        }
    }

    // quad reduce (tq lanes), then cross-colgroup reduce via smem
#pragma unroll
    for (int j = 0; j < 4; j++) {
        rsum[j] += __shfl_xor_sync(0xFFFFFFFF, rsum[j], 1);
        rsum[j] += __shfl_xor_sync(0xFFFFFFFF, rsum[j], 2);
    }
    __syncthreads();
    if (tq == 0) {
#pragma unroll
        for (int mi = 0; mi < 2; mi++)
#pragma unroll
            for (int h = 0; h < 2; h++)
                s_red[cgw * 64 + m0 + mi * 16 + h * 8 + gq] = rsum[mi * 2 + h];
    }
    __syncthreads();
    if (tid < 64)
        g_u[row0 + tid] = (s_red[tid] + s_red[64 + tid])
                        + (s_red[128 + tid] + s_red[192 + tid]);
}

// ==================== kernel 4: masked softmax + candidate collection ====================
__global__ void __launch_bounds__(256)
tail1_kernel(const int* __restrict__ mask, float* __restrict__ out_a) {
    int b = blockIdx.x, tid = threadIdx.x;           // 256 threads
    __shared__ float red[256];
    __shared__ int   ncand;

    const float* ub = g_u + b * NT;
    const int* mb = mask + b * NT;
    float* ab = out_a + b * NT;

    float mx = -3.4e38f;
    for (int t = tid; t < NT; t += 256) {
        float um = ub[t] + (mb[t] ? 0.f : -1e20f);
        mx = fmaxf(mx, um);
    }
    red[tid] = mx; __syncthreads();
    for (int s = 128; s > 0; s >>= 1) { if (tid < s) red[tid] = fmaxf(red[tid], red[tid + s]); __syncthreads(); }
    mx = red[0];
    if (tid == 0) ncand = 0;
    __syncthreads();

    float sum = 0.f;
    for (int t = tid; t < NT; t += 256) {
        float um = ub[t] + (mb[t] ? 0.f : -1e20f);
        float e = expf(um - mx);
        ab[t] = e;
        sum += e;
        if (um > mx - 0.01f) {                       // fp16 GEMM u-error ~1e-3 << 0.01
            int p = atomicAdd(&ncand, 1);
            if (p < MAXC) g_cand[b * MAXC + p] = t;
        }
    }
    red[tid] = sum; __syncthreads();
    for (int s = 128; s > 0; s >>= 1) { if (tid < s) red[tid] += red[tid + s]; __syncthreads(); }
    float inv = 1.0f / red[0];
    __syncthreads();
    for (int t = tid; t < NT; t += 256) ab[t] *= inv;
    if (tid == 0) g_ncand[b] = min(ncand, MAXC);
}

// ==================== kernel 5: exact-fp32 candidate re-score (1 CTA / candidate) ====
__global__ void __launch_bounds__(512)
tail2_kernel(const float* __restrict__ value, const float* __restrict__ W1,
             const float* __restrict__ Vvec) {
    const int b = blockIdx.x, ci = blockIdx.y, tid = threadIdx.x;   // 512 threads
    if (ci >= g_ncand[b]) return;
    const int t = g_cand[b * MAXC + ci];

    __shared__ float sval[ND];
    __shared__ float red[512];

    sval[tid] = value[((size_t)b * NT + t) * ND + tid];
    __syncthreads();

    float s1 = 0.f;
#pragma unroll 8
    for (int d = 0; d < ND; d++) s1 += sval[d] * W1[(size_t)d * NU + tid];
    float p = Vvec[tid] * tanhf(s1 + g_w2q[b * NU + tid]);

    red[tid] = p; __syncthreads();
    for (int s = 256; s > 0; s >>= 1) { if (tid < s) red[tid] += red[tid + s]; __syncthreads(); }
    if (tid == 0)
        atomicMax(&g_best[b], pack_key(red[0], t));
}

// ==================== kernel 6: gather context ====================
__global__ void __launch_bounds__(512)
tail3_kernel(const float* __restrict__ value, float* __restrict__ out_ctx) {
    const int b = blockIdx.x, tid = threadIdx.x;     // 512 threads
    const int t = 2047 - (int)(g_best[b] & 0xFFFFFFFFull);
    out_ctx[b * ND + tid] = value[((size_t)b * NT + t) * ND + tid];
}

// ==================== launch ====================
extern "C" void kernel_launch(void* const* d_in, const int* in_sizes, int n_in,
                              void* d_out, int out_size) {
    const float* value = (const float*)d_in[0];   // [32, 2048, 512]
    const float* query = (const float*)d_in[1];   // [32, 512]
    const int*   mask  = (const int*)d_in[2];     // [32, 2048]
    const float* W1    = (const float*)d_in[3];   // [512, 512]
    const float* W2    = (const float*)d_in[4];   // [512, 512]
    const float* Vv    = (const float*)d_in[5];   // [512]

    float* out     = (float*)d_out;
    float* out_ctx = out;                         // context [32, 512] first
    float* out_a   = out + NBATCH * ND;           // then a [32, 2048]

    cudaFuncSetAttribute(attn_main, cudaFuncAttributeMaxDynamicSharedMemorySize, SMEM_BYTES);

    prep_w1t<<<dim3(NU / 32, ND / 32), dim3(32, 8)>>>(W1);          // idx 0
    prep_w2q<<<NBATCH, 512>>>(query, W2);                            // idx 1
    init_best<<<1, 32>>>();                                          // idx 2
    attn_main<<<(NBATCH * NT) / 64, 256, SMEM_BYTES>>>(value, Vv);   // idx 3 (profiled)
    tail1_kernel<<<NBATCH, 256>>>(mask, out_a);
    tail2_kernel<<<dim3(NBATCH, MAXC), 512>>>(value, W1, Vv);
    tail3_kernel<<<NBATCH, 512>>>(value, out_ctx);
}